// round 1
// baseline (speedup 1.0000x reference)
#include <cuda_runtime.h>
#include <math.h>

#define NU 60001
#define NI 40001
#define NN 100002
#define DD 64
#define EE 600000
#define NB 2048

// ---- scratch (static device globals; no allocation allowed) ----
__device__ __align__(128) float d_X0 [NN * DD];   // total0
__device__ __align__(128) float d_ALL[NN * DD];   // all_emb (global GCN out)
__device__ __align__(128) float d_T1 [NN * DD];   // layer-1 scratch
__device__ __align__(128) float d_T2 [NN * DD];   // layer-2 scratch
__device__ __align__(128) float d_AU [NU * 3 * DD]; // all_user (60001,3,64)
__device__ __align__(128) float d_AI [NI * 3 * DD]; // all_item (40001,3,64)
__device__ __align__(128) float d_IF [NI * DD];     // item_final
__device__ __align__(128) float d_DEG[NN];
__device__ __align__(128) float d_IBD[NI * 3];
__device__ __align__(128) float d_ACC[4];

// ---- degree count ----
__global__ void k_deg(const int* __restrict__ eu, const int* __restrict__ ei,
                      int E, float* __restrict__ deg) {
    int e = blockIdx.x * blockDim.x + threadIdx.x;
    if (e >= E) return;
    atomicAdd(&deg[eu[e]], 1.0f);
    atomicAdd(&deg[ei[e] + NU], 1.0f);
}

// ---- one propagation layer: out += norm * inp over both edge directions ----
// One warp per edge. Lanes 0-15: inp[u] row -> out[item]; lanes 16-31: inp[item] -> out[u].
// Each lane moves one float4 and issues one vector RED.
__global__ void k_scatter(const float* __restrict__ inp, float* __restrict__ out,
                          const int* __restrict__ eu, const int* __restrict__ ei,
                          const float* __restrict__ deg, int E) {
    int t = blockIdx.x * blockDim.x + threadIdx.x;
    int e = t >> 5;
    if (e >= E) return;
    int lane = t & 31;
    int u  = eu[e];
    int it = ei[e] + NU;
    float w = rsqrtf(fmaxf(deg[u], 1.0f)) * rsqrtf(fmaxf(deg[it], 1.0f));
    int g = lane >> 4;          // direction
    int c = lane & 15;          // float4 chunk within row
    long rs = (long)(g ? it : u) * DD;
    long rd = (long)(g ? u : it) * DD;
    float4 v = __ldg((const float4*)(inp + rs) + c);
    v.x *= w; v.y *= w; v.z *= w; v.w *= w;
    float* p = out + rd + 4 * c;
    asm volatile("red.global.add.v4.f32 [%0], {%1,%2,%3,%4};"
                 :: "l"(p), "f"(v.x), "f"(v.y), "f"(v.z), "f"(v.w) : "memory");
}

// ---- out = (a + b + c) / 3 ----
__global__ void k_comb(const float* __restrict__ a, const float* __restrict__ b,
                       const float* __restrict__ c, float* __restrict__ o, int n4) {
    int i = blockIdx.x * blockDim.x + threadIdx.x;
    if (i >= n4) return;
    float4 x = ((const float4*)a)[i];
    float4 y = ((const float4*)b)[i];
    float4 z = ((const float4*)c)[i];
    const float s = 1.0f / 3.0f;
    float4 r;
    r.x = (x.x + y.x + z.x) * s;
    r.y = (x.y + y.y + z.y) * s;
    r.z = (x.z + y.z + z.z) * s;
    r.w = (x.w + y.w + z.w) * s;
    ((float4*)o)[i] = r;
}

// ---- combine and split into per-branch user/item stacks ----
__global__ void k_comb_split(const float* __restrict__ a, const float* __restrict__ b,
                             const float* __restrict__ c, float* __restrict__ au,
                             float* __restrict__ ai, int bidx) {
    int i = blockIdx.x * blockDim.x + threadIdx.x;
    if (i >= NN * 16) return;
    int node = i >> 4;
    int ch   = i & 15;
    float4 x = ((const float4*)a)[i];
    float4 y = ((const float4*)b)[i];
    float4 z = ((const float4*)c)[i];
    const float s = 1.0f / 3.0f;
    float4 r;
    r.x = (x.x + y.x + z.x) * s;
    r.y = (x.y + y.y + z.y) * s;
    r.z = (x.z + y.z + z.z) * s;
    r.w = (x.w + y.w + z.w) * s;
    if (node < NU)
        ((float4*)au)[(long)node * 48 + bidx * 16 + ch] = r;
    else
        ((float4*)ai)[(long)(node - NU) * 48 + bidx * 16 + ch] = r;
}

// ---- mutual attention, in-place on AU. One warp per user. ----
__global__ void k_att(float* __restrict__ au, int n) {
    int t = blockIdx.x * blockDim.x + threadIdx.x;
    int u = t >> 5;
    if (u >= n) return;
    int lane = t & 31;
    float2* base = (float2*)au + (long)u * 96;
    float2 f0 = base[lane];
    float2 f1 = base[32 + lane];
    float2 f2 = base[64 + lane];
    float s00 = f0.x * f0.x + f0.y * f0.y;
    float s01 = f0.x * f1.x + f0.y * f1.y;
    float s02 = f0.x * f2.x + f0.y * f2.y;
    float s11 = f1.x * f1.x + f1.y * f1.y;
    float s12 = f1.x * f2.x + f1.y * f2.y;
    float s22 = f2.x * f2.x + f2.y * f2.y;
    #pragma unroll
    for (int o = 16; o; o >>= 1) {
        s00 += __shfl_xor_sync(0xffffffffu, s00, o);
        s01 += __shfl_xor_sync(0xffffffffu, s01, o);
        s02 += __shfl_xor_sync(0xffffffffu, s02, o);
        s11 += __shfl_xor_sync(0xffffffffu, s11, o);
        s12 += __shfl_xor_sync(0xffffffffu, s12, o);
        s22 += __shfl_xor_sync(0xffffffffu, s22, o);
    }
    // last = S[2][:] = (s02, s12, s22)
    float l0 = s02, l1 = s12, l2 = s22;
    float q0 = l0 * l0 / (l0 * l0 + 1e-12f);
    float q1 = l1 * l1 / (l1 * l1 + 1e-12f);
    float q2 = l2 * l2 / (l2 * l2 + 1e-12f);
    // clear rows (i=0 uses S[0][:], i=1 uses S[1][:])
    float c00 = s00 * q0, c01 = s01 * q1, c02 = s02 * q2;
    float c10 = s01 * q0, c11 = s11 * q1, c12 = s12 * q2;
    float r20 = c00 + c10 + l0;
    float r21 = c01 + c11 + l1;
    float r22 = c02 + c12 + l2;
    float att[3][3] = {{c00, c01, c02}, {c10, c11, c12}, {r20, r21, r22}};
    #pragma unroll
    for (int i = 0; i < 3; i++) {
        float m = fmaxf(att[i][0], fmaxf(att[i][1], att[i][2]));
        float e0 = expf((att[i][0] - m) * 0.125f);
        float e1 = expf((att[i][1] - m) * 0.125f);
        float e2 = expf((att[i][2] - m) * 0.125f);
        float inv = 1.0f / (e0 + e1 + e2);
        att[i][0] = e0 * inv; att[i][1] = e1 * inv; att[i][2] = e2 * inv;
    }
    #pragma unroll
    for (int i = 0; i < 3; i++) {
        float2 o;
        o.x = att[i][0] * f0.x + att[i][1] * f1.x + att[i][2] * f2.x;
        o.y = att[i][0] * f0.y + att[i][1] * f1.y + att[i][2] * f2.y;
        base[i * 32 + lane] = o;
    }
}

// ---- per-branch item degree counts ----
__global__ void k_ibd(const int* __restrict__ ei, float* __restrict__ ibd) {
    int t = blockIdx.x * blockDim.x + threadIdx.x;
    if (t >= 3 * EE) return;
    int b = t / EE;
    atomicAdd(&ibd[ei[t] * 3 + b], 1.0f);
}

// ---- item_final = sum_b all_item[:,b,:] * weight[:,b] ----
__global__ void k_if(const float* __restrict__ ai, const float* __restrict__ ibd,
                     const float* __restrict__ W, float* __restrict__ ifl) {
    int t = blockIdx.x * blockDim.x + threadIdx.x;
    int i = t >> 5;
    if (i >= NI) return;
    int lane = t & 31;
    float w0 = ibd[i * 3 + 0] * W[0];
    float w1 = ibd[i * 3 + 1] * W[1];
    float w2 = ibd[i * 3 + 2] * W[2];
    float inv = 1.0f / (w0 + w1 + w2 + 1e-8f);
    w0 *= inv; w1 *= inv; w2 *= inv;
    const float2* a = (const float2*)ai + (long)i * 96;
    float2 v0 = a[lane], v1 = a[32 + lane], v2 = a[64 + lane];
    float2 r;
    r.x = v0.x * w0 + v1.x * w1 + v2.x * w2;
    r.y = v0.y * w0 + v1.y * w1 + v2.y * w2;
    ((float2*)ifl)[(long)i * 32 + lane] = r;
}

// ---- BPR loss: one warp per (sample, branch) ----
__global__ void k_bpr(const int* __restrict__ batch, const float* __restrict__ au,
                      const float* __restrict__ ifl, float* __restrict__ acc) {
    int t = blockIdx.x * blockDim.x + threadIdx.x;
    int idx = t >> 5;
    if (idx >= NB * 3) return;
    int lane = t & 31;
    int n = idx / 3, b = idx % 3;
    const int* bd = batch + n * 9 + b * 3;
    int u = bd[0], pos = bd[1], neg = bd[2];
    float2 uf = ((const float2*)au)[(long)u * 96 + b * 32 + lane];
    float2 p  = ((const float2*)ifl)[(long)pos * 32 + lane];
    float2 q  = ((const float2*)ifl)[(long)neg * 32 + lane];
    float s = uf.x * (p.x - q.x) + uf.y * (p.y - q.y);
    #pragma unroll
    for (int o = 16; o; o >>= 1) s += __shfl_xor_sync(0xffffffffu, s, o);
    if (lane == 0) {
        float sig = 1.0f / (1.0f + expf(-s));
        float val = logf(1e-10f + sig);
        atomicAdd(acc, -val * (1.0f / (float)NB));
    }
}

// ---- sum of squares reduction ----
__global__ void k_sumsq(const float* __restrict__ x, int n, float* __restrict__ acc) {
    float s = 0.0f;
    for (int i = blockIdx.x * blockDim.x + threadIdx.x; i < n; i += gridDim.x * blockDim.x) {
        float v = x[i];
        s += v * v;
    }
    #pragma unroll
    for (int o = 16; o; o >>= 1) s += __shfl_xor_sync(0xffffffffu, s, o);
    if ((threadIdx.x & 31) == 0) atomicAdd(acc, s);
}

__global__ void k_final(const float* __restrict__ acc, float* __restrict__ out) {
    out[0] = acc[0] + 0.001f * (sqrtf(acc[1]) + sqrtf(acc[2])) / 40001.0f;
}

extern "C" void kernel_launch(void* const* d_in, const int* in_sizes, int n_in,
                              void* d_out, int out_size) {
    const float* user_emb = (const float*)d_in[0];
    const float* item_emb = (const float*)d_in[1];
    const float* W        = (const float*)d_in[2];
    const int*   eu       = (const int*)d_in[3];
    const int*   ei       = (const int*)d_in[4];
    const int*   batch    = (const int*)d_in[5];
    float* out = (float*)d_out;

    float *X0, *ALL, *T1, *T2, *AU, *AI, *IF, *DEG, *IBD, *ACC;
    cudaGetSymbolAddress((void**)&X0,  d_X0);
    cudaGetSymbolAddress((void**)&ALL, d_ALL);
    cudaGetSymbolAddress((void**)&T1,  d_T1);
    cudaGetSymbolAddress((void**)&T2,  d_T2);
    cudaGetSymbolAddress((void**)&AU,  d_AU);
    cudaGetSymbolAddress((void**)&AI,  d_AI);
    cudaGetSymbolAddress((void**)&IF,  d_IF);
    cudaGetSymbolAddress((void**)&DEG, d_DEG);
    cudaGetSymbolAddress((void**)&IBD, d_IBD);
    cudaGetSymbolAddress((void**)&ACC, d_ACC);

    const size_t embBytes = (size_t)NN * DD * sizeof(float);
    const int NTH = 256;
    const int EG  = 3 * EE;                                   // global edge count
    auto blocksFor = [](long threads) { return (int)((threads + 255) / 256); };

    // total0 = concat(user_emb, item_emb)
    cudaMemcpyAsync(X0, user_emb, (size_t)NU * DD * sizeof(float), cudaMemcpyDeviceToDevice);
    cudaMemcpyAsync(X0 + (size_t)NU * DD, item_emb, (size_t)NI * DD * sizeof(float),
                    cudaMemcpyDeviceToDevice);

    // ---- global LightGCN ----
    cudaMemsetAsync(DEG, 0, NN * sizeof(float));
    k_deg<<<blocksFor(EG), NTH>>>(eu, ei, EG, DEG);
    cudaMemsetAsync(T1, 0, embBytes);
    k_scatter<<<blocksFor((long)EG * 32), NTH>>>(X0, T1, eu, ei, DEG, EG);
    cudaMemsetAsync(T2, 0, embBytes);
    k_scatter<<<blocksFor((long)EG * 32), NTH>>>(T1, T2, eu, ei, DEG, EG);
    k_comb<<<blocksFor(NN * 16), NTH>>>(X0, T1, T2, ALL, NN * 16);

    // ---- per-branch LightGCNs ----
    for (int b = 0; b < 3; b++) {
        const int* eub = eu + (size_t)b * EE;
        const int* eib = ei + (size_t)b * EE;
        cudaMemsetAsync(DEG, 0, NN * sizeof(float));
        k_deg<<<blocksFor(EE), NTH>>>(eub, eib, EE, DEG);
        cudaMemsetAsync(T1, 0, embBytes);
        k_scatter<<<blocksFor((long)EE * 32), NTH>>>(ALL, T1, eub, eib, DEG, EE);
        cudaMemsetAsync(T2, 0, embBytes);
        k_scatter<<<blocksFor((long)EE * 32), NTH>>>(T1, T2, eub, eib, DEG, EE);
        k_comb_split<<<blocksFor(NN * 16), NTH>>>(ALL, T1, T2, AU, AI, b);
    }

    // ---- mutual attention on users ----
    k_att<<<blocksFor((long)NU * 32), NTH>>>(AU, NU);

    // ---- item weighting ----
    cudaMemsetAsync(IBD, 0, NI * 3 * sizeof(float));
    k_ibd<<<blocksFor(3 * EE), NTH>>>(ei, IBD);
    k_if<<<blocksFor((long)NI * 32), NTH>>>(AI, IBD, W, IF);

    // ---- losses ----
    cudaMemsetAsync(ACC, 0, 4 * sizeof(float));
    k_bpr<<<blocksFor((long)NB * 3 * 32), NTH>>>(batch, AU, IF, ACC);
    k_sumsq<<<512, NTH>>>(user_emb, NU * DD, ACC + 1);
    k_sumsq<<<512, NTH>>>(item_emb, NI * DD, ACC + 2);
    k_final<<<1, 1>>>(ACC, out);
}

// round 2
// speedup vs baseline: 1.8440x; 1.8440x over previous
#include <cuda_runtime.h>
#include <math.h>

#define NU 60001
#define NI 40001
#define NN 100002
#define DD 64
#define EE 600000
#define E2 (2*EE)
#define NB 2048
#define NCH 98   // ceil(NN/1024)

// ---- static device scratch ----
__device__ __align__(128) float d_X0 [NN * DD];     // total0
__device__ __align__(128) float d_T1 [NN * DD];     // global layer-1
__device__ __align__(128) float d_ALL[NN * DD];     // global GCN output
__device__ __align__(128) float d_TB [3 * NN * DD]; // branch layer-1 (3 branches)
__device__ __align__(128) float d_AU [NU * 3 * DD]; // all_user (post-attention)
__device__ __align__(128) float d_IF [NI * DD];     // item_final
__device__ __align__(128) int   d_adj [3 * E2];     // per-branch directed adjacency
__device__ __align__(128) int   d_deg [3 * NN];     // per-branch degrees
__device__ __align__(128) int   d_off [3 * (NN + 1)];
__device__ __align__(128) int   d_cur [3 * NN];
__device__ __align__(128) int   d_sums[3 * NCH];
__device__ __align__(128) float d_rnG [NN];         // rsqrt(global degree)
__device__ __align__(128) float d_rnB [3 * NN];     // rsqrt(branch degree)
__device__ float d_ACC[4];

// ---- degree count (per branch) ----
__global__ void k_degcnt(const int* __restrict__ eu, const int* __restrict__ ei,
                         int* __restrict__ deg) {
    int t = blockIdx.x * blockDim.x + threadIdx.x;
    if (t >= 3 * EE) return;
    int b = t / EE;
    atomicAdd(&deg[b * NN + eu[t]], 1);
    atomicAdd(&deg[b * NN + NU + ei[t]], 1);
}

// ---- 3-pass exclusive scan: chunk scan / chunk-total scan / add base ----
__global__ void k_scanA(const int* __restrict__ deg, int* __restrict__ off,
                        int* __restrict__ sums) {
    int g = blockIdx.x / NCH, c = blockIdx.x % NCH;
    int i = c * 1024 + threadIdx.x;
    int v = (i < NN) ? deg[g * NN + i] : 0;
    __shared__ int sd[1024];
    sd[threadIdx.x] = v;
    __syncthreads();
    for (int o = 1; o < 1024; o <<= 1) {
        int a = (threadIdx.x >= o) ? sd[threadIdx.x - o] : 0;
        __syncthreads();
        sd[threadIdx.x] += a;
        __syncthreads();
    }
    int inc = sd[threadIdx.x];
    if (i < NN) off[g * (NN + 1) + i] = inc - v;   // chunk-local exclusive
    if (threadIdx.x == 1023) sums[g * NCH + c] = inc;
}

__global__ void k_scanB(int* __restrict__ sums) {
    int g = blockIdx.x, t = threadIdx.x;
    __shared__ int sd[128];
    int v = (t < NCH) ? sums[g * NCH + t] : 0;
    sd[t] = v;
    __syncthreads();
    for (int o = 1; o < 128; o <<= 1) {
        int a = (t >= o) ? sd[t - o] : 0;
        __syncthreads();
        sd[t] += a;
        __syncthreads();
    }
    if (t < NCH) sums[g * NCH + t] = sd[t] - v;    // exclusive chunk base
}

__global__ void k_scanC(int* __restrict__ off, const int* __restrict__ sums,
                        int* __restrict__ cur) {
    int g = blockIdx.x / NCH, c = blockIdx.x % NCH;
    int i = c * 1024 + threadIdx.x;
    if (i < NN) {
        int o = off[g * (NN + 1) + i] + sums[g * NCH + c];
        off[g * (NN + 1) + i] = o;
        cur[g * NN + i] = o;
    }
    if (i == NN - 1) off[g * (NN + 1) + NN] = E2;
}

// ---- rsqrt of degrees ----
__global__ void k_rnorm(const int* __restrict__ deg, float* __restrict__ rnG,
                        float* __restrict__ rnB) {
    int i = blockIdx.x * blockDim.x + threadIdx.x;
    if (i >= NN) return;
    int d0 = deg[i], d1 = deg[NN + i], d2 = deg[2 * NN + i];
    rnB[i]          = rsqrtf((float)max(d0, 1));
    rnB[NN + i]     = rsqrtf((float)max(d1, 1));
    rnB[2 * NN + i] = rsqrtf((float)max(d2, 1));
    rnG[i] = rsqrtf((float)max(d0 + d1 + d2, 1));
}

// ---- adjacency placement ----
__global__ void k_place(const int* __restrict__ eu, const int* __restrict__ ei,
                        int* __restrict__ cur, int* __restrict__ adj) {
    int t = blockIdx.x * blockDim.x + threadIdx.x;
    if (t >= 3 * EE) return;
    int b = t / EE;
    int u = eu[t], it = NU + ei[t];
    int p = atomicAdd(&cur[b * NN + u], 1);
    adj[b * E2 + p] = it;
    int q = atomicAdd(&cur[b * NN + it], 1);
    adj[b * E2 + q] = u;
}

// ---- gather inner loop: acc += rn[src] * inp[src] over one adjacency list ----
__device__ __forceinline__ void gath(const float* __restrict__ inp,
                                     const int* __restrict__ adj,
                                     int s, int e, const float* __restrict__ rn,
                                     int lane2, float2& acc) {
    int j = s;
    for (; j + 4 <= e; j += 4) {
        int s0 = __ldg(adj + j), s1 = __ldg(adj + j + 1);
        int s2 = __ldg(adj + j + 2), s3 = __ldg(adj + j + 3);
        float w0 = __ldg(rn + s0), w1 = __ldg(rn + s1);
        float w2 = __ldg(rn + s2), w3 = __ldg(rn + s3);
        float2 v0 = __ldg((const float2*)(inp + (size_t)s0 * DD + lane2));
        float2 v1 = __ldg((const float2*)(inp + (size_t)s1 * DD + lane2));
        float2 v2 = __ldg((const float2*)(inp + (size_t)s2 * DD + lane2));
        float2 v3 = __ldg((const float2*)(inp + (size_t)s3 * DD + lane2));
        acc.x += w0 * v0.x + w1 * v1.x + w2 * v2.x + w3 * v3.x;
        acc.y += w0 * v0.y + w1 * v1.y + w2 * v2.y + w3 * v3.y;
    }
    for (; j < e; j++) {
        int s0 = __ldg(adj + j);
        float w0 = __ldg(rn + s0);
        float2 v0 = __ldg((const float2*)(inp + (size_t)s0 * DD + lane2));
        acc.x += w0 * v0.x;
        acc.y += w0 * v0.y;
    }
}

// ---- global GCN layer 1: T1 = S_g(X0) (union of 3 branch lists) ----
__global__ void k_gL1(const float* __restrict__ inp, float* __restrict__ out,
                      const int* __restrict__ off, const int* __restrict__ adj,
                      const float* __restrict__ rnG) {
    int t = blockIdx.x * blockDim.x + threadIdx.x;
    int n = t >> 5;
    if (n >= NN) return;
    int lane2 = (t & 31) * 2;
    float2 acc = {0.f, 0.f};
    #pragma unroll
    for (int g = 0; g < 3; g++) {
        int s = off[g * (NN + 1) + n], e = off[g * (NN + 1) + n + 1];
        gath(inp, adj + (size_t)g * E2, s, e, rnG, lane2, acc);
    }
    float rd = rnG[n];
    *(float2*)(out + (size_t)n * DD + lane2) = make_float2(acc.x * rd, acc.y * rd);
}

// ---- global GCN layer 2 + combine: ALL = (X0 + T1 + S_g(T1)) / 3 ----
__global__ void k_gL2c(const float* __restrict__ x0, const float* __restrict__ t1,
                       float* __restrict__ allo, const int* __restrict__ off,
                       const int* __restrict__ adj, const float* __restrict__ rnG) {
    int t = blockIdx.x * blockDim.x + threadIdx.x;
    int n = t >> 5;
    if (n >= NN) return;
    int lane2 = (t & 31) * 2;
    float2 acc = {0.f, 0.f};
    #pragma unroll
    for (int g = 0; g < 3; g++) {
        int s = off[g * (NN + 1) + n], e = off[g * (NN + 1) + n + 1];
        gath(t1, adj + (size_t)g * E2, s, e, rnG, lane2, acc);
    }
    float rd = rnG[n];
    float2 a = __ldg((const float2*)(x0 + (size_t)n * DD + lane2));
    float2 b = __ldg((const float2*)(t1 + (size_t)n * DD + lane2));
    const float s3 = 1.0f / 3.0f;
    *(float2*)(allo + (size_t)n * DD + lane2) =
        make_float2((a.x + b.x + acc.x * rd) * s3, (a.y + b.y + acc.y * rd) * s3);
}

// ---- branch layer 1 (all 3 branches): TB[g] = S_b(ALL) ----
__global__ void k_bL1(const float* __restrict__ allo, float* __restrict__ tb,
                      const int* __restrict__ off, const int* __restrict__ adj,
                      const float* __restrict__ rnB) {
    int t = blockIdx.x * blockDim.x + threadIdx.x;
    int q = t >> 5;
    if (q >= 3 * NN) return;
    int g = q / NN, n = q - g * NN;
    int lane2 = (t & 31) * 2;
    const float* rn = rnB + (size_t)g * NN;
    float2 acc = {0.f, 0.f};
    int s = off[g * (NN + 1) + n], e = off[g * (NN + 1) + n + 1];
    gath(allo, adj + (size_t)g * E2, s, e, rn, lane2, acc);
    float rd = rn[n];
    *(float2*)(tb + (size_t)g * NN * DD + (size_t)n * DD + lane2) =
        make_float2(acc.x * rd, acc.y * rd);
}

// ---- branch layer 2 + combine + attention (users) / weighting (items) ----
__global__ void k_bL2f(const float* __restrict__ allo, const float* __restrict__ tb,
                       const int* __restrict__ off, const int* __restrict__ adj,
                       const float* __restrict__ rnB, const int* __restrict__ deg,
                       const float* __restrict__ W, float* __restrict__ au,
                       float* __restrict__ ifl) {
    int t = blockIdx.x * blockDim.x + threadIdx.x;
    int n = t >> 5;
    if (n >= NN) return;
    int lane = t & 31;
    int lane2 = lane * 2;
    float2 a = __ldg((const float2*)(allo + (size_t)n * DD + lane2));
    float2 f[3];
    const float s3 = 1.0f / 3.0f;
    #pragma unroll
    for (int g = 0; g < 3; g++) {
        const float* src = tb + (size_t)g * NN * DD;
        const float* rn = rnB + (size_t)g * NN;
        float2 b = __ldg((const float2*)(src + (size_t)n * DD + lane2));
        float2 acc = {0.f, 0.f};
        int s = off[g * (NN + 1) + n], e = off[g * (NN + 1) + n + 1];
        gath(src, adj + (size_t)g * E2, s, e, rn, lane2, acc);
        float rd = rn[n];
        f[g] = make_float2((a.x + b.x + acc.x * rd) * s3,
                           (a.y + b.y + acc.y * rd) * s3);
    }
    if (n < NU) {
        // mutual attention on (f0,f1,f2)
        float s00 = f[0].x * f[0].x + f[0].y * f[0].y;
        float s01 = f[0].x * f[1].x + f[0].y * f[1].y;
        float s02 = f[0].x * f[2].x + f[0].y * f[2].y;
        float s11 = f[1].x * f[1].x + f[1].y * f[1].y;
        float s12 = f[1].x * f[2].x + f[1].y * f[2].y;
        float s22 = f[2].x * f[2].x + f[2].y * f[2].y;
        #pragma unroll
        for (int o = 16; o; o >>= 1) {
            s00 += __shfl_xor_sync(0xffffffffu, s00, o);
            s01 += __shfl_xor_sync(0xffffffffu, s01, o);
            s02 += __shfl_xor_sync(0xffffffffu, s02, o);
            s11 += __shfl_xor_sync(0xffffffffu, s11, o);
            s12 += __shfl_xor_sync(0xffffffffu, s12, o);
            s22 += __shfl_xor_sync(0xffffffffu, s22, o);
        }
        float l0 = s02, l1 = s12, l2 = s22;
        float q0 = l0 * l0 / (l0 * l0 + 1e-12f);
        float q1 = l1 * l1 / (l1 * l1 + 1e-12f);
        float q2 = l2 * l2 / (l2 * l2 + 1e-12f);
        float c00 = s00 * q0, c01 = s01 * q1, c02 = s02 * q2;
        float c10 = s01 * q0, c11 = s11 * q1, c12 = s12 * q2;
        float r20 = c00 + c10 + l0;
        float r21 = c01 + c11 + l1;
        float r22 = c02 + c12 + l2;
        float att[3][3] = {{c00, c01, c02}, {c10, c11, c12}, {r20, r21, r22}};
        #pragma unroll
        for (int i = 0; i < 3; i++) {
            float m = fmaxf(att[i][0], fmaxf(att[i][1], att[i][2]));
            float e0 = expf((att[i][0] - m) * 0.125f);
            float e1 = expf((att[i][1] - m) * 0.125f);
            float e2 = expf((att[i][2] - m) * 0.125f);
            float inv = 1.0f / (e0 + e1 + e2);
            att[i][0] = e0 * inv; att[i][1] = e1 * inv; att[i][2] = e2 * inv;
        }
        float2* base = (float2*)au + (size_t)n * 96;
        #pragma unroll
        for (int i = 0; i < 3; i++) {
            float2 o;
            o.x = att[i][0] * f[0].x + att[i][1] * f[1].x + att[i][2] * f[2].x;
            o.y = att[i][0] * f[0].y + att[i][1] * f[1].y + att[i][2] * f[2].y;
            base[i * 32 + lane] = o;
        }
    } else {
        int i = n - NU;
        float w0 = (float)__ldg(deg + n)          * __ldg(W + 0);
        float w1 = (float)__ldg(deg + NN + n)     * __ldg(W + 1);
        float w2 = (float)__ldg(deg + 2 * NN + n) * __ldg(W + 2);
        float inv = 1.0f / (w0 + w1 + w2 + 1e-8f);
        w0 *= inv; w1 *= inv; w2 *= inv;
        float2 r;
        r.x = f[0].x * w0 + f[1].x * w1 + f[2].x * w2;
        r.y = f[0].y * w0 + f[1].y * w1 + f[2].y * w2;
        *(float2*)(ifl + (size_t)i * DD + lane2) = r;
    }
}

// ---- BPR loss ----
__global__ void k_bpr(const int* __restrict__ batch, const float* __restrict__ au,
                      const float* __restrict__ ifl, float* __restrict__ acc) {
    int t = blockIdx.x * blockDim.x + threadIdx.x;
    int idx = t >> 5;
    if (idx >= NB * 3) return;
    int lane = t & 31;
    int n = idx / 3, b = idx % 3;
    const int* bd = batch + n * 9 + b * 3;
    int u = bd[0], pos = bd[1], neg = bd[2];
    float2 uf = ((const float2*)au)[(size_t)u * 96 + b * 32 + lane];
    float2 p  = ((const float2*)ifl)[(size_t)pos * 32 + lane];
    float2 q  = ((const float2*)ifl)[(size_t)neg * 32 + lane];
    float s = uf.x * (p.x - q.x) + uf.y * (p.y - q.y);
    #pragma unroll
    for (int o = 16; o; o >>= 1) s += __shfl_xor_sync(0xffffffffu, s, o);
    if (lane == 0) {
        float sig = 1.0f / (1.0f + expf(-s));
        atomicAdd(acc, -logf(1e-10f + sig) * (1.0f / (float)NB));
    }
}

__global__ void k_sumsq(const float* __restrict__ x, int n, float* __restrict__ acc) {
    float s = 0.0f;
    for (int i = blockIdx.x * blockDim.x + threadIdx.x; i < n; i += gridDim.x * blockDim.x) {
        float v = x[i];
        s += v * v;
    }
    #pragma unroll
    for (int o = 16; o; o >>= 1) s += __shfl_xor_sync(0xffffffffu, s, o);
    if ((threadIdx.x & 31) == 0) atomicAdd(acc, s);
}

__global__ void k_final(const float* __restrict__ acc, float* __restrict__ out) {
    out[0] = acc[0] + 0.001f * (sqrtf(acc[1]) + sqrtf(acc[2])) / 40001.0f;
}

extern "C" void kernel_launch(void* const* d_in, const int* in_sizes, int n_in,
                              void* d_out, int out_size) {
    const float* user_emb = (const float*)d_in[0];
    const float* item_emb = (const float*)d_in[1];
    const float* W        = (const float*)d_in[2];
    const int*   eu       = (const int*)d_in[3];
    const int*   ei       = (const int*)d_in[4];
    const int*   batch    = (const int*)d_in[5];
    float* out = (float*)d_out;

    float *X0, *T1, *ALL, *TB, *AU, *IF, *rnG, *rnB, *ACC;
    int *adj, *deg, *off, *cur, *sums;
    cudaGetSymbolAddress((void**)&X0,  d_X0);
    cudaGetSymbolAddress((void**)&T1,  d_T1);
    cudaGetSymbolAddress((void**)&ALL, d_ALL);
    cudaGetSymbolAddress((void**)&TB,  d_TB);
    cudaGetSymbolAddress((void**)&AU,  d_AU);
    cudaGetSymbolAddress((void**)&IF,  d_IF);
    cudaGetSymbolAddress((void**)&rnG, d_rnG);
    cudaGetSymbolAddress((void**)&rnB, d_rnB);
    cudaGetSymbolAddress((void**)&ACC, d_ACC);
    cudaGetSymbolAddress((void**)&adj, d_adj);
    cudaGetSymbolAddress((void**)&deg, d_deg);
    cudaGetSymbolAddress((void**)&off, d_off);
    cudaGetSymbolAddress((void**)&cur, d_cur);
    cudaGetSymbolAddress((void**)&sums, d_sums);

    const int NTH = 256;
    auto blocksFor = [](long threads) { return (int)((threads + 255) / 256); };

    // X0 = concat(user_emb, item_emb)
    cudaMemcpyAsync(X0, user_emb, (size_t)NU * DD * sizeof(float), cudaMemcpyDeviceToDevice);
    cudaMemcpyAsync(X0 + (size_t)NU * DD, item_emb, (size_t)NI * DD * sizeof(float),
                    cudaMemcpyDeviceToDevice);

    // ---- CSR build ----
    cudaMemsetAsync(deg, 0, 3 * NN * sizeof(int));
    k_degcnt<<<blocksFor(3L * EE), NTH>>>(eu, ei, deg);
    k_scanA<<<3 * NCH, 1024>>>(deg, off, sums);
    k_scanB<<<3, 128>>>(sums);
    k_scanC<<<3 * NCH, 1024>>>(off, sums, cur);
    k_rnorm<<<blocksFor(NN), NTH>>>(deg, rnG, rnB);
    k_place<<<blocksFor(3L * EE), NTH>>>(eu, ei, cur, adj);

    // ---- global LightGCN (2 layers + combine) ----
    k_gL1<<<blocksFor((long)NN * 32), NTH>>>(X0, T1, off, adj, rnG);
    k_gL2c<<<blocksFor((long)NN * 32), NTH>>>(X0, T1, ALL, off, adj, rnG);

    // ---- branch LightGCNs: layer1 (all 3), layer2 fused w/ attention + weighting ----
    k_bL1<<<blocksFor(3L * NN * 32), NTH>>>(ALL, TB, off, adj, rnB);
    k_bL2f<<<blocksFor((long)NN * 32), NTH>>>(ALL, TB, off, adj, rnB, deg, W, AU, IF);

    // ---- losses ----
    cudaMemsetAsync(ACC, 0, 4 * sizeof(float));
    k_bpr<<<blocksFor((long)NB * 3 * 32), NTH>>>(batch, AU, IF, ACC);
    k_sumsq<<<512, NTH>>>(user_emb, NU * DD, ACC + 1);
    k_sumsq<<<512, NTH>>>(item_emb, NI * DD, ACC + 2);
    k_final<<<1, 1>>>(ACC, out);
}

// round 4
// speedup vs baseline: 2.1635x; 1.1733x over previous
#include <cuda_runtime.h>
#include <cuda_fp16.h>
#include <math.h>

#define NU 60001
#define NI 40001
#define NN 100002
#define DD 64
#define EE 600000
#define E2 (2*EE)
#define NB 2048
#define NCH 98   // ceil(NN/1024)

// ---- static device scratch ----
__device__ __align__(128) __half d_X0h [NN * DD];     // total0 (fp16)
__device__ __align__(128) __half d_T1h [NN * DD];     // global layer-1 (fp16)
__device__ __align__(128) __half d_ALLh[NN * DD];     // global GCN output (fp16)
__device__ __align__(128) __half d_TBh [3 * NN * DD]; // branch layer-1 (fp16)
__device__ __align__(128) float  d_AU [NU * 3 * DD];  // all_user (post-attention, fp32)
__device__ __align__(128) float  d_IF [NI * DD];      // item_final (fp32)
__device__ __align__(128) int    d_adj [3 * E2];      // per-branch directed adjacency
__device__ __align__(128) int    d_deg [3 * NN];      // per-branch degrees
__device__ __align__(128) int    d_off [3 * (NN + 1)];
__device__ __align__(128) int    d_cur [3 * NN];
__device__ __align__(128) int    d_sums[3 * NCH];
__device__ __align__(128) float  d_rnG [NN];          // rsqrt(global degree)
__device__ __align__(128) float  d_rnB [3 * NN];      // rsqrt(branch degree)
__device__ float d_ACC[4];

// ---- convert inputs to fp16 X0 ----
__global__ void k_conv(const float* __restrict__ ue, const float* __restrict__ ie,
                       __half* __restrict__ x0h) {
    int i = blockIdx.x * blockDim.x + threadIdx.x;       // half2 index
    if (i >= NN * DD / 2) return;
    int elem = i * 2;
    const int UB = NU * DD;
    float2 v = (elem < UB) ? __ldg((const float2*)(ue + elem))
                           : __ldg((const float2*)(ie + (elem - UB)));
    ((__half2*)x0h)[i] = __float22half2_rn(v);
}

// ---- degree count (per branch) ----
__global__ void k_degcnt(const int* __restrict__ eu, const int* __restrict__ ei,
                         int* __restrict__ deg) {
    int t = blockIdx.x * blockDim.x + threadIdx.x;
    if (t >= 3 * EE) return;
    int b = t / EE;
    atomicAdd(&deg[b * NN + eu[t]], 1);
    atomicAdd(&deg[b * NN + NU + ei[t]], 1);
}

// ---- 3-pass exclusive scan ----
__global__ void k_scanA(const int* __restrict__ deg, int* __restrict__ off,
                        int* __restrict__ sums) {
    int g = blockIdx.x / NCH, c = blockIdx.x % NCH;
    int i = c * 1024 + threadIdx.x;
    int v = (i < NN) ? deg[g * NN + i] : 0;
    __shared__ int sd[1024];
    sd[threadIdx.x] = v;
    __syncthreads();
    for (int o = 1; o < 1024; o <<= 1) {
        int a = (threadIdx.x >= o) ? sd[threadIdx.x - o] : 0;
        __syncthreads();
        sd[threadIdx.x] += a;
        __syncthreads();
    }
    int inc = sd[threadIdx.x];
    if (i < NN) off[g * (NN + 1) + i] = inc - v;
    if (threadIdx.x == 1023) sums[g * NCH + c] = inc;
}

__global__ void k_scanB(int* __restrict__ sums) {
    int g = blockIdx.x, t = threadIdx.x;
    __shared__ int sd[128];
    int v = (t < NCH) ? sums[g * NCH + t] : 0;
    sd[t] = v;
    __syncthreads();
    for (int o = 1; o < 128; o <<= 1) {
        int a = (t >= o) ? sd[t - o] : 0;
        __syncthreads();
        sd[t] += a;
        __syncthreads();
    }
    if (t < NCH) sums[g * NCH + t] = sd[t] - v;
}

__global__ void k_scanC(int* __restrict__ off, const int* __restrict__ sums,
                        int* __restrict__ cur) {
    int g = blockIdx.x / NCH, c = blockIdx.x % NCH;
    int i = c * 1024 + threadIdx.x;
    if (i < NN) {
        int o = off[g * (NN + 1) + i] + sums[g * NCH + c];
        off[g * (NN + 1) + i] = o;
        cur[g * NN + i] = o;
    }
    if (i == NN - 1) off[g * (NN + 1) + NN] = E2;
}

// ---- rsqrt of degrees ----
__global__ void k_rnorm(const int* __restrict__ deg, float* __restrict__ rnG,
                        float* __restrict__ rnB) {
    int i = blockIdx.x * blockDim.x + threadIdx.x;
    if (i >= NN) return;
    int d0 = deg[i], d1 = deg[NN + i], d2 = deg[2 * NN + i];
    rnB[i]          = rsqrtf((float)max(d0, 1));
    rnB[NN + i]     = rsqrtf((float)max(d1, 1));
    rnB[2 * NN + i] = rsqrtf((float)max(d2, 1));
    rnG[i] = rsqrtf((float)max(d0 + d1 + d2, 1));
}

// ---- adjacency placement ----
__global__ void k_place(const int* __restrict__ eu, const int* __restrict__ ei,
                        int* __restrict__ cur, int* __restrict__ adj) {
    int t = blockIdx.x * blockDim.x + threadIdx.x;
    if (t >= 3 * EE) return;
    int b = t / EE;
    int u = eu[t], it = NU + ei[t];
    int p = atomicAdd(&cur[b * NN + u], 1);
    adj[b * E2 + p] = it;
    int q = atomicAdd(&cur[b * NN + it], 1);
    adj[b * E2 + q] = u;
}

// ---- gather inner loop (fp16 rows, fp32 accumulate) ----
__device__ __forceinline__ void gath(const __half* __restrict__ inp,
                                     const int* __restrict__ adj,
                                     int s, int e, const float* __restrict__ rn,
                                     int lane2, float2& acc) {
    int j = s;
    for (; j + 4 <= e; j += 4) {
        int s0 = __ldg(adj + j), s1 = __ldg(adj + j + 1);
        int s2 = __ldg(adj + j + 2), s3 = __ldg(adj + j + 3);
        float w0 = __ldg(rn + s0), w1 = __ldg(rn + s1);
        float w2 = __ldg(rn + s2), w3 = __ldg(rn + s3);
        float2 v0 = __half22float2(__ldg((const __half2*)(inp + (size_t)s0 * DD + lane2)));
        float2 v1 = __half22float2(__ldg((const __half2*)(inp + (size_t)s1 * DD + lane2)));
        float2 v2 = __half22float2(__ldg((const __half2*)(inp + (size_t)s2 * DD + lane2)));
        float2 v3 = __half22float2(__ldg((const __half2*)(inp + (size_t)s3 * DD + lane2)));
        acc.x += w0 * v0.x + w1 * v1.x + w2 * v2.x + w3 * v3.x;
        acc.y += w0 * v0.y + w1 * v1.y + w2 * v2.y + w3 * v3.y;
    }
    for (; j < e; j++) {
        int s0 = __ldg(adj + j);
        float w0 = __ldg(rn + s0);
        float2 v0 = __half22float2(__ldg((const __half2*)(inp + (size_t)s0 * DD + lane2)));
        acc.x += w0 * v0.x;
        acc.y += w0 * v0.y;
    }
}

// ---- global GCN layer 1: T1 = S_g(X0) ----
__global__ void k_gL1(const __half* __restrict__ inp, __half* __restrict__ out,
                      const int* __restrict__ off, const int* __restrict__ adj,
                      const float* __restrict__ rnG) {
    int t = blockIdx.x * blockDim.x + threadIdx.x;
    int n = t >> 5;
    if (n >= NN) return;
    int lane2 = (t & 31) * 2;
    float2 acc = {0.f, 0.f};
    #pragma unroll
    for (int g = 0; g < 3; g++) {
        int s = off[g * (NN + 1) + n], e = off[g * (NN + 1) + n + 1];
        gath(inp, adj + (size_t)g * E2, s, e, rnG, lane2, acc);
    }
    float rd = rnG[n];
    *(__half2*)(out + (size_t)n * DD + lane2) =
        __float22half2_rn(make_float2(acc.x * rd, acc.y * rd));
}

// ---- global GCN layer 2 + combine: ALL = (X0 + T1 + S_g(T1)) / 3 ----
__global__ void k_gL2c(const __half* __restrict__ x0, const __half* __restrict__ t1,
                       __half* __restrict__ allo, const int* __restrict__ off,
                       const int* __restrict__ adj, const float* __restrict__ rnG) {
    int t = blockIdx.x * blockDim.x + threadIdx.x;
    int n = t >> 5;
    if (n >= NN) return;
    int lane2 = (t & 31) * 2;
    float2 acc = {0.f, 0.f};
    #pragma unroll
    for (int g = 0; g < 3; g++) {
        int s = off[g * (NN + 1) + n], e = off[g * (NN + 1) + n + 1];
        gath(t1, adj + (size_t)g * E2, s, e, rnG, lane2, acc);
    }
    float rd = rnG[n];
    float2 a = __half22float2(__ldg((const __half2*)(x0 + (size_t)n * DD + lane2)));
    float2 b = __half22float2(__ldg((const __half2*)(t1 + (size_t)n * DD + lane2)));
    const float s3 = 1.0f / 3.0f;
    *(__half2*)(allo + (size_t)n * DD + lane2) =
        __float22half2_rn(make_float2((a.x + b.x + acc.x * rd) * s3,
                                      (a.y + b.y + acc.y * rd) * s3));
}

// ---- branch layer 1 (all 3 branches): TB[g] = S_b(ALL) ----
__global__ void k_bL1(const __half* __restrict__ allo, __half* __restrict__ tb,
                      const int* __restrict__ off, const int* __restrict__ adj,
                      const float* __restrict__ rnB) {
    int t = blockIdx.x * blockDim.x + threadIdx.x;
    int q = t >> 5;
    if (q >= 3 * NN) return;
    int g = q / NN, n = q - g * NN;
    int lane2 = (t & 31) * 2;
    const float* rn = rnB + (size_t)g * NN;
    float2 acc = {0.f, 0.f};
    int s = off[g * (NN + 1) + n], e = off[g * (NN + 1) + n + 1];
    gath(allo, adj + (size_t)g * E2, s, e, rn, lane2, acc);
    float rd = rn[n];
    *(__half2*)(tb + (size_t)g * NN * DD + (size_t)n * DD + lane2) =
        __float22half2_rn(make_float2(acc.x * rd, acc.y * rd));
}

// ---- branch layer 2 + combine + attention (users) / weighting (items) ----
__global__ void k_bL2f(const __half* __restrict__ allo, const __half* __restrict__ tb,
                       const int* __restrict__ off, const int* __restrict__ adj,
                       const float* __restrict__ rnB, const int* __restrict__ deg,
                       const float* __restrict__ W, float* __restrict__ au,
                       float* __restrict__ ifl) {
    int t = blockIdx.x * blockDim.x + threadIdx.x;
    int n = t >> 5;
    if (n >= NN) return;
    int lane = t & 31;
    int lane2 = lane * 2;
    float2 a = __half22float2(__ldg((const __half2*)(allo + (size_t)n * DD + lane2)));
    float2 f[3];
    const float s3 = 1.0f / 3.0f;
    #pragma unroll
    for (int g = 0; g < 3; g++) {
        const __half* src = tb + (size_t)g * NN * DD;
        const float* rn = rnB + (size_t)g * NN;
        float2 b = __half22float2(__ldg((const __half2*)(src + (size_t)n * DD + lane2)));
        float2 acc = {0.f, 0.f};
        int s = off[g * (NN + 1) + n], e = off[g * (NN + 1) + n + 1];
        gath(src, adj + (size_t)g * E2, s, e, rn, lane2, acc);
        float rd = rn[n];
        f[g] = make_float2((a.x + b.x + acc.x * rd) * s3,
                           (a.y + b.y + acc.y * rd) * s3);
    }
    if (n < NU) {
        float s00 = f[0].x * f[0].x + f[0].y * f[0].y;
        float s01 = f[0].x * f[1].x + f[0].y * f[1].y;
        float s02 = f[0].x * f[2].x + f[0].y * f[2].y;
        float s11 = f[1].x * f[1].x + f[1].y * f[1].y;
        float s12 = f[1].x * f[2].x + f[1].y * f[2].y;
        float s22 = f[2].x * f[2].x + f[2].y * f[2].y;
        #pragma unroll
        for (int o = 16; o; o >>= 1) {
            s00 += __shfl_xor_sync(0xffffffffu, s00, o);
            s01 += __shfl_xor_sync(0xffffffffu, s01, o);
            s02 += __shfl_xor_sync(0xffffffffu, s02, o);
            s11 += __shfl_xor_sync(0xffffffffu, s11, o);
            s12 += __shfl_xor_sync(0xffffffffu, s12, o);
            s22 += __shfl_xor_sync(0xffffffffu, s22, o);
        }
        float l0 = s02, l1 = s12, l2 = s22;
        float q0 = l0 * l0 / (l0 * l0 + 1e-12f);
        float q1 = l1 * l1 / (l1 * l1 + 1e-12f);
        float q2 = l2 * l2 / (l2 * l2 + 1e-12f);
        float c00 = s00 * q0, c01 = s01 * q1, c02 = s02 * q2;
        float c10 = s01 * q0, c11 = s11 * q1, c12 = s12 * q2;
        float r20 = c00 + c10 + l0;
        float r21 = c01 + c11 + l1;
        float r22 = c02 + c12 + l2;
        float att[3][3] = {{c00, c01, c02}, {c10, c11, c12}, {r20, r21, r22}};
        #pragma unroll
        for (int i = 0; i < 3; i++) {
            float m = fmaxf(att[i][0], fmaxf(att[i][1], att[i][2]));
            float e0 = expf((att[i][0] - m) * 0.125f);
            float e1 = expf((att[i][1] - m) * 0.125f);
            float e2 = expf((att[i][2] - m) * 0.125f);
            float inv = 1.0f / (e0 + e1 + e2);
            att[i][0] = e0 * inv; att[i][1] = e1 * inv; att[i][2] = e2 * inv;
        }
        float2* base = (float2*)au + (size_t)n * 96;
        #pragma unroll
        for (int i = 0; i < 3; i++) {
            float2 o;
            o.x = att[i][0] * f[0].x + att[i][1] * f[1].x + att[i][2] * f[2].x;
            o.y = att[i][0] * f[0].y + att[i][1] * f[1].y + att[i][2] * f[2].y;
            base[i * 32 + lane] = o;
        }
    } else {
        int i = n - NU;
        float w0 = (float)__ldg(deg + n)          * __ldg(W + 0);
        float w1 = (float)__ldg(deg + NN + n)     * __ldg(W + 1);
        float w2 = (float)__ldg(deg + 2 * NN + n) * __ldg(W + 2);
        float inv = 1.0f / (w0 + w1 + w2 + 1e-8f);
        w0 *= inv; w1 *= inv; w2 *= inv;
        float2 r;
        r.x = f[0].x * w0 + f[1].x * w1 + f[2].x * w2;
        r.y = f[0].y * w0 + f[1].y * w1 + f[2].y * w2;
        *(float2*)(ifl + (size_t)i * DD + lane2) = r;
    }
}

// ---- BPR loss ----
__global__ void k_bpr(const int* __restrict__ batch, const float* __restrict__ au,
                      const float* __restrict__ ifl, float* __restrict__ acc) {
    int t = blockIdx.x * blockDim.x + threadIdx.x;
    int idx = t >> 5;
    if (idx >= NB * 3) return;
    int lane = t & 31;
    int n = idx / 3, b = idx % 3;
    const int* bd = batch + n * 9 + b * 3;
    int u = bd[0], pos = bd[1], neg = bd[2];
    float2 uf = ((const float2*)au)[(size_t)u * 96 + b * 32 + lane];
    float2 p  = ((const float2*)ifl)[(size_t)pos * 32 + lane];
    float2 q  = ((const float2*)ifl)[(size_t)neg * 32 + lane];
    float s = uf.x * (p.x - q.x) + uf.y * (p.y - q.y);
    #pragma unroll
    for (int o = 16; o; o >>= 1) s += __shfl_xor_sync(0xffffffffu, s, o);
    if (lane == 0) {
        float sig = 1.0f / (1.0f + expf(-s));
        atomicAdd(acc, -logf(1e-10f + sig) * (1.0f / (float)NB));
    }
}

__global__ void k_sumsq(const float* __restrict__ x, int n, float* __restrict__ acc) {
    float s = 0.0f;
    for (int i = blockIdx.x * blockDim.x + threadIdx.x; i < n; i += gridDim.x * blockDim.x) {
        float v = x[i];
        s += v * v;
    }
    #pragma unroll
    for (int o = 16; o; o >>= 1) s += __shfl_xor_sync(0xffffffffu, s, o);
    if ((threadIdx.x & 31) == 0) atomicAdd(acc, s);
}

__global__ void k_final(const float* __restrict__ acc, float* __restrict__ out) {
    out[0] = acc[0] + 0.001f * (sqrtf(acc[1]) + sqrtf(acc[2])) / 40001.0f;
}

extern "C" void kernel_launch(void* const* d_in, const int* in_sizes, int n_in,
                              void* d_out, int out_size) {
    const float* user_emb = (const float*)d_in[0];
    const float* item_emb = (const float*)d_in[1];
    const float* W        = (const float*)d_in[2];
    const int*   eu       = (const int*)d_in[3];
    const int*   ei       = (const int*)d_in[4];
    const int*   batch    = (const int*)d_in[5];
    float* out = (float*)d_out;

    __half *X0h, *T1h, *ALLh, *TBh;
    float *AU, *IF, *rnG, *rnB, *ACC;
    int *adj, *deg, *off, *cur, *sums;
    cudaGetSymbolAddress((void**)&X0h,  d_X0h);
    cudaGetSymbolAddress((void**)&T1h,  d_T1h);
    cudaGetSymbolAddress((void**)&ALLh, d_ALLh);
    cudaGetSymbolAddress((void**)&TBh,  d_TBh);
    cudaGetSymbolAddress((void**)&AU,   d_AU);
    cudaGetSymbolAddress((void**)&IF,   d_IF);
    cudaGetSymbolAddress((void**)&rnG,  d_rnG);
    cudaGetSymbolAddress((void**)&rnB,  d_rnB);
    cudaGetSymbolAddress((void**)&ACC,  d_ACC);
    cudaGetSymbolAddress((void**)&adj,  d_adj);
    cudaGetSymbolAddress((void**)&deg,  d_deg);
    cudaGetSymbolAddress((void**)&off,  d_off);
    cudaGetSymbolAddress((void**)&cur,  d_cur);
    cudaGetSymbolAddress((void**)&sums, d_sums);

    const int NTH = 256;
    auto blocksFor = [](long threads) { return (int)((threads + 255) / 256); };

    // X0 (fp16) = concat(user_emb, item_emb)
    k_conv<<<blocksFor((long)NN * DD / 2), NTH>>>(user_emb, item_emb, X0h);

    // ---- CSR build ----
    cudaMemsetAsync(deg, 0, 3 * NN * sizeof(int));
    k_degcnt<<<blocksFor(3L * EE), NTH>>>(eu, ei, deg);
    k_scanA<<<3 * NCH, 1024>>>(deg, off, sums);
    k_scanB<<<3, 128>>>(sums);
    k_scanC<<<3 * NCH, 1024>>>(off, sums, cur);
    k_rnorm<<<blocksFor(NN), NTH>>>(deg, rnG, rnB);
    k_place<<<blocksFor(3L * EE), NTH>>>(eu, ei, cur, adj);

    // ---- global LightGCN (2 layers + combine) ----
    k_gL1<<<blocksFor((long)NN * 32), NTH>>>(X0h, T1h, off, adj, rnG);
    k_gL2c<<<blocksFor((long)NN * 32), NTH>>>(X0h, T1h, ALLh, off, adj, rnG);

    // ---- branch LightGCNs ----
    k_bL1<<<blocksFor(3L * NN * 32), NTH>>>(ALLh, TBh, off, adj, rnB);
    k_bL2f<<<blocksFor((long)NN * 32), NTH>>>(ALLh, TBh, off, adj, rnB, deg, W, AU, IF);

    // ---- losses ----
    cudaMemsetAsync(ACC, 0, 4 * sizeof(float));
    k_bpr<<<blocksFor((long)NB * 3 * 32), NTH>>>(batch, AU, IF, ACC);
    k_sumsq<<<512, NTH>>>(user_emb, NU * DD, ACC + 1);
    k_sumsq<<<512, NTH>>>(item_emb, NI * DD, ACC + 2);
    k_final<<<1, 1>>>(ACC, out);
}

// round 6
// speedup vs baseline: 2.1787x; 1.0070x over previous
#include <cuda_runtime.h>
#include <cuda_fp16.h>
#include <math.h>

#define NU 60001
#define NI 40001
#define NN 100002
#define DD 64
#define EE 600000
#define E2 (2*EE)
#define NB 2048
#define NCH 98   // ceil(NN/1024)

// ---- static device scratch ----
__device__ __align__(128) __half d_X0h [NN * DD];     // total0 (fp16)
__device__ __align__(128) __half d_T1h [NN * DD];     // global layer-1 (fp16)
__device__ __align__(128) __half d_ALLh[NN * DD];     // global GCN output (fp16)
__device__ __align__(128) __half d_TBh [3 * NN * DD]; // branch layer-1 (fp16)
__device__ __align__(128) float  d_AU [NU * 3 * DD];  // all_user row-major [u][3][64]
__device__ __align__(128) float  d_IF [NI * DD];      // item_final row-major
__device__ __align__(128) int    d_adj [3 * E2];
__device__ __align__(128) int    d_deg [3 * NN];
__device__ __align__(128) int    d_off [3 * (NN + 1)];
__device__ __align__(128) int    d_cur [3 * NN];
__device__ __align__(128) int    d_sums[3 * NCH];
__device__ __align__(128) float  d_rnG [NN];
__device__ __align__(128) float  d_rnB [3 * NN];
__device__ float d_ACC[4];

// ---- convert inputs to fp16 X0 ----
__global__ void k_conv(const float* __restrict__ ue, const float* __restrict__ ie,
                       __half* __restrict__ x0h) {
    int i = blockIdx.x * blockDim.x + threadIdx.x;       // half2 index
    if (i >= NN * DD / 2) return;
    int elem = i * 2;
    const int UB = NU * DD;
    float2 v = (elem < UB) ? __ldg((const float2*)(ue + elem))
                           : __ldg((const float2*)(ie + (elem - UB)));
    ((__half2*)x0h)[i] = __float22half2_rn(v);
}

// ---- degree count ----
__global__ void k_degcnt(const int* __restrict__ eu, const int* __restrict__ ei,
                         int* __restrict__ deg) {
    int t = blockIdx.x * blockDim.x + threadIdx.x;
    if (t >= 3 * EE) return;
    int b = t / EE;
    atomicAdd(&deg[b * NN + eu[t]], 1);
    atomicAdd(&deg[b * NN + NU + ei[t]], 1);
}

// ---- 3-pass exclusive scan ----
__global__ void k_scanA(const int* __restrict__ deg, int* __restrict__ off,
                        int* __restrict__ sums) {
    int g = blockIdx.x / NCH, c = blockIdx.x % NCH;
    int i = c * 1024 + threadIdx.x;
    int v = (i < NN) ? deg[g * NN + i] : 0;
    __shared__ int sd[1024];
    sd[threadIdx.x] = v;
    __syncthreads();
    for (int o = 1; o < 1024; o <<= 1) {
        int a = (threadIdx.x >= o) ? sd[threadIdx.x - o] : 0;
        __syncthreads();
        sd[threadIdx.x] += a;
        __syncthreads();
    }
    int inc = sd[threadIdx.x];
    if (i < NN) off[g * (NN + 1) + i] = inc - v;
    if (threadIdx.x == 1023) sums[g * NCH + c] = inc;
}

__global__ void k_scanB(int* __restrict__ sums) {
    int g = blockIdx.x, t = threadIdx.x;
    __shared__ int sd[128];
    int v = (t < NCH) ? sums[g * NCH + t] : 0;
    sd[t] = v;
    __syncthreads();
    for (int o = 1; o < 128; o <<= 1) {
        int a = (t >= o) ? sd[t - o] : 0;
        __syncthreads();
        sd[t] += a;
        __syncthreads();
    }
    if (t < NCH) sums[g * NCH + t] = sd[t] - v;
}

__global__ void k_scanC(int* __restrict__ off, const int* __restrict__ sums,
                        int* __restrict__ cur) {
    int g = blockIdx.x / NCH, c = blockIdx.x % NCH;
    int i = c * 1024 + threadIdx.x;
    if (i < NN) {
        int o = off[g * (NN + 1) + i] + sums[g * NCH + c];
        off[g * (NN + 1) + i] = o;
        cur[g * NN + i] = o;
    }
    if (i == NN - 1) off[g * (NN + 1) + NN] = E2;
}

// ---- rsqrt of degrees ----
__global__ void k_rnorm(const int* __restrict__ deg, float* __restrict__ rnG,
                        float* __restrict__ rnB) {
    int i = blockIdx.x * blockDim.x + threadIdx.x;
    if (i >= NN) return;
    int d0 = deg[i], d1 = deg[NN + i], d2 = deg[2 * NN + i];
    rnB[i]          = rsqrtf((float)max(d0, 1));
    rnB[NN + i]     = rsqrtf((float)max(d1, 1));
    rnB[2 * NN + i] = rsqrtf((float)max(d2, 1));
    rnG[i] = rsqrtf((float)max(d0 + d1 + d2, 1));
}

// ---- adjacency placement ----
__global__ void k_place(const int* __restrict__ eu, const int* __restrict__ ei,
                        int* __restrict__ cur, int* __restrict__ adj) {
    int t = blockIdx.x * blockDim.x + threadIdx.x;
    if (t >= 3 * EE) return;
    int b = t / EE;
    int u = eu[t], it = NU + ei[t];
    int p = atomicAdd(&cur[b * NN + u], 1);
    adj[b * E2 + p] = it;
    int q = atomicAdd(&cur[b * NN + it], 1);
    adj[b * E2 + q] = u;
}

// ---- 4-neighbor-wide gather: group g handles neighbor j+g, lane chunk c
//      loads 16B (8 halves = dims c*8..c*8+7). acc[8] in fp32. ----
__device__ __forceinline__ void gath4(const __half* __restrict__ inp,
                                      const int* __restrict__ adj,
                                      int s, int e, const float* __restrict__ rn,
                                      int g, int c, float* __restrict__ acc) {
    for (int j = s; j < e; j += 4) {
        int jj = j + g;
        bool act = jj < e;
        int idx = act ? __ldg(adj + jj) : 0;
        float w = act ? __ldg(rn + idx) : 0.0f;
        int4 raw = __ldg((const int4*)(inp + (size_t)idx * DD + c * 8));
        __half2* h = (__half2*)&raw;
        #pragma unroll
        for (int k = 0; k < 4; k++) {
            float2 v = __half22float2(h[k]);
            acc[2 * k]     += w * v.x;
            acc[2 * k + 1] += w * v.y;
        }
    }
}

// butterfly-reduce acc[8] across the 4 lane groups (offsets 8,16)
__device__ __forceinline__ void red4(float* __restrict__ acc) {
    #pragma unroll
    for (int k = 0; k < 8; k++) {
        acc[k] += __shfl_xor_sync(0xffffffffu, acc[k], 8);
        acc[k] += __shfl_xor_sync(0xffffffffu, acc[k], 16);
    }
}

// lanes g==0 store 8 dims (scaled) as fp16 int4
__device__ __forceinline__ void store_h(__half* __restrict__ out, size_t n,
                                        int g, int c, const float* __restrict__ acc,
                                        float scale) {
    if (g == 0) {
        __half2 h[4];
        #pragma unroll
        for (int k = 0; k < 4; k++)
            h[k] = __float22half2_rn(make_float2(acc[2 * k] * scale,
                                                 acc[2 * k + 1] * scale));
        *(int4*)(out + n * DD + c * 8) = *(int4*)h;
    }
}

// ---- global GCN layer 1: T1 = S_g(X0) ----
__global__ void k_gL1(const __half* __restrict__ inp, __half* __restrict__ out,
                      const int* __restrict__ off, const int* __restrict__ adj,
                      const float* __restrict__ rnG) {
    int t = blockIdx.x * blockDim.x + threadIdx.x;
    int n = t >> 5;
    if (n >= NN) return;
    int lane = t & 31, g = lane >> 3, c = lane & 7;
    float acc[8] = {0, 0, 0, 0, 0, 0, 0, 0};
    #pragma unroll
    for (int gg = 0; gg < 3; gg++) {
        int s = off[gg * (NN + 1) + n], e = off[gg * (NN + 1) + n + 1];
        gath4(inp, adj + (size_t)gg * E2, s, e, rnG, g, c, acc);
    }
    red4(acc);
    store_h(out, n, g, c, acc, rnG[n]);
}

// ---- global GCN layer 2 + combine: ALL = (X0 + T1 + S_g(T1)) / 3 ----
__global__ void k_gL2c(const __half* __restrict__ x0, const __half* __restrict__ t1,
                       __half* __restrict__ allo, const int* __restrict__ off,
                       const int* __restrict__ adj, const float* __restrict__ rnG) {
    int t = blockIdx.x * blockDim.x + threadIdx.x;
    int n = t >> 5;
    if (n >= NN) return;
    int lane = t & 31, g = lane >> 3, c = lane & 7;
    float acc[8] = {0, 0, 0, 0, 0, 0, 0, 0};
    #pragma unroll
    for (int gg = 0; gg < 3; gg++) {
        int s = off[gg * (NN + 1) + n], e = off[gg * (NN + 1) + n + 1];
        gath4(t1, adj + (size_t)gg * E2, s, e, rnG, g, c, acc);
    }
    red4(acc);
    if (g == 0) {
        float rd = rnG[n];
        int4 ra = __ldg((const int4*)(x0 + (size_t)n * DD + c * 8));
        int4 rb = __ldg((const int4*)(t1 + (size_t)n * DD + c * 8));
        __half2* ha = (__half2*)&ra;
        __half2* hb = (__half2*)&rb;
        const float s3 = 1.0f / 3.0f;
        __half2 hout[4];
        #pragma unroll
        for (int k = 0; k < 4; k++) {
            float2 a = __half22float2(ha[k]);
            float2 b = __half22float2(hb[k]);
            hout[k] = __float22half2_rn(
                make_float2((a.x + b.x + acc[2 * k] * rd) * s3,
                            (a.y + b.y + acc[2 * k + 1] * rd) * s3));
        }
        *(int4*)(allo + (size_t)n * DD + c * 8) = *(int4*)hout;
    }
}

// ---- branch layer 1 (all 3 branches): TB[g] = S_b(ALL) ----
__global__ void k_bL1(const __half* __restrict__ allo, __half* __restrict__ tb,
                      const int* __restrict__ off, const int* __restrict__ adj,
                      const float* __restrict__ rnB) {
    int t = blockIdx.x * blockDim.x + threadIdx.x;
    int q = t >> 5;
    if (q >= 3 * NN) return;
    int gg = q / NN, n = q - gg * NN;
    int lane = t & 31, g = lane >> 3, c = lane & 7;
    const float* rn = rnB + (size_t)gg * NN;
    float acc[8] = {0, 0, 0, 0, 0, 0, 0, 0};
    int s = off[gg * (NN + 1) + n], e = off[gg * (NN + 1) + n + 1];
    gath4(allo, adj + (size_t)gg * E2, s, e, rn, g, c, acc);
    red4(acc);
    store_h(tb + (size_t)gg * NN * DD, n, g, c, acc, rn[n]);
}

// ---- branch layer 2 + combine + attention (users) / weighting (items) ----
__global__ void k_bL2f(const __half* __restrict__ allo, const __half* __restrict__ tb,
                       const int* __restrict__ off, const int* __restrict__ adj,
                       const float* __restrict__ rnB, const int* __restrict__ deg,
                       const float* __restrict__ W, float* __restrict__ au,
                       float* __restrict__ ifl) {
    int t = blockIdx.x * blockDim.x + threadIdx.x;
    int n = t >> 5;
    if (n >= NN) return;
    int lane = t & 31, g = lane >> 3, c = lane & 7;
    // a = ALL row (dims c*8..): broadcast per chunk, every lane keeps it
    int4 ra = __ldg((const int4*)(allo + (size_t)n * DD + c * 8));
    __half2* ha = (__half2*)&ra;
    float f[3][8];
    const float s3 = 1.0f / 3.0f;
    #pragma unroll
    for (int gg = 0; gg < 3; gg++) {
        const __half* src = tb + (size_t)gg * NN * DD;
        const float* rn = rnB + (size_t)gg * NN;
        float acc[8] = {0, 0, 0, 0, 0, 0, 0, 0};
        int s = off[gg * (NN + 1) + n], e = off[gg * (NN + 1) + n + 1];
        gath4(src, adj + (size_t)gg * E2, s, e, rn, g, c, acc);
        red4(acc);
        float rd = rn[n];
        int4 rb = __ldg((const int4*)(src + (size_t)n * DD + c * 8));
        __half2* hb = (__half2*)&rb;
        #pragma unroll
        for (int k = 0; k < 4; k++) {
            float2 a = __half22float2(ha[k]);
            float2 b = __half22float2(hb[k]);
            f[gg][2 * k]     = (a.x + b.x + acc[2 * k] * rd) * s3;
            f[gg][2 * k + 1] = (a.y + b.y + acc[2 * k + 1] * rd) * s3;
        }
    }
    if (n < NU) {
        // dot products over 64 dims: per-lane partial over its 8 dims,
        // reduce within the 8-lane chunk axis (offsets 1,2,4). dims are
        // replicated across the 4 groups, so every lane gets the full sum.
        float s00 = 0, s01 = 0, s02 = 0, s11 = 0, s12 = 0, s22 = 0;
        #pragma unroll
        for (int k = 0; k < 8; k++) {
            s00 += f[0][k] * f[0][k];
            s01 += f[0][k] * f[1][k];
            s02 += f[0][k] * f[2][k];
            s11 += f[1][k] * f[1][k];
            s12 += f[1][k] * f[2][k];
            s22 += f[2][k] * f[2][k];
        }
        #pragma unroll
        for (int o = 1; o < 8; o <<= 1) {
            s00 += __shfl_xor_sync(0xffffffffu, s00, o);
            s01 += __shfl_xor_sync(0xffffffffu, s01, o);
            s02 += __shfl_xor_sync(0xffffffffu, s02, o);
            s11 += __shfl_xor_sync(0xffffffffu, s11, o);
            s12 += __shfl_xor_sync(0xffffffffu, s12, o);
            s22 += __shfl_xor_sync(0xffffffffu, s22, o);
        }
        float l0 = s02, l1 = s12, l2 = s22;
        float q0 = l0 * l0 / (l0 * l0 + 1e-12f);
        float q1 = l1 * l1 / (l1 * l1 + 1e-12f);
        float q2 = l2 * l2 / (l2 * l2 + 1e-12f);
        float c00 = s00 * q0, c01 = s01 * q1, c02 = s02 * q2;
        float c10 = s01 * q0, c11 = s11 * q1, c12 = s12 * q2;
        float r20 = c00 + c10 + l0;
        float r21 = c01 + c11 + l1;
        float r22 = c02 + c12 + l2;
        float att[3][3] = {{c00, c01, c02}, {c10, c11, c12}, {r20, r21, r22}};
        #pragma unroll
        for (int i = 0; i < 3; i++) {
            float m = fmaxf(att[i][0], fmaxf(att[i][1], att[i][2]));
            float e0 = expf((att[i][0] - m) * 0.125f);
            float e1 = expf((att[i][1] - m) * 0.125f);
            float e2 = expf((att[i][2] - m) * 0.125f);
            float inv = 1.0f / (e0 + e1 + e2);
            att[i][0] = e0 * inv; att[i][1] = e1 * inv; att[i][2] = e2 * inv;
        }
        if (g == 0) {
            float* base = au + (size_t)n * 192;   // [u][3][64]
            #pragma unroll
            for (int i = 0; i < 3; i++) {
                float4 o0, o1;
                o0.x = att[i][0] * f[0][0] + att[i][1] * f[1][0] + att[i][2] * f[2][0];
                o0.y = att[i][0] * f[0][1] + att[i][1] * f[1][1] + att[i][2] * f[2][1];
                o0.z = att[i][0] * f[0][2] + att[i][1] * f[1][2] + att[i][2] * f[2][2];
                o0.w = att[i][0] * f[0][3] + att[i][1] * f[1][3] + att[i][2] * f[2][3];
                o1.x = att[i][0] * f[0][4] + att[i][1] * f[1][4] + att[i][2] * f[2][4];
                o1.y = att[i][0] * f[0][5] + att[i][1] * f[1][5] + att[i][2] * f[2][5];
                o1.z = att[i][0] * f[0][6] + att[i][1] * f[1][6] + att[i][2] * f[2][6];
                o1.w = att[i][0] * f[0][7] + att[i][1] * f[1][7] + att[i][2] * f[2][7];
                *(float4*)(base + i * 64 + c * 8)     = o0;
                *(float4*)(base + i * 64 + c * 8 + 4) = o1;
            }
        }
    } else {
        if (g == 0) {
            int i = n - NU;
            float w0 = (float)__ldg(deg + n)          * __ldg(W + 0);
            float w1 = (float)__ldg(deg + NN + n)     * __ldg(W + 1);
            float w2 = (float)__ldg(deg + 2 * NN + n) * __ldg(W + 2);
            float inv = 1.0f / (w0 + w1 + w2 + 1e-8f);
            w0 *= inv; w1 *= inv; w2 *= inv;
            float4 o0, o1;
            o0.x = f[0][0] * w0 + f[1][0] * w1 + f[2][0] * w2;
            o0.y = f[0][1] * w0 + f[1][1] * w1 + f[2][1] * w2;
            o0.z = f[0][2] * w0 + f[1][2] * w1 + f[2][2] * w2;
            o0.w = f[0][3] * w0 + f[1][3] * w1 + f[2][3] * w2;
            o1.x = f[0][4] * w0 + f[1][4] * w1 + f[2][4] * w2;
            o1.y = f[0][5] * w0 + f[1][5] * w1 + f[2][5] * w2;
            o1.z = f[0][6] * w0 + f[1][6] * w1 + f[2][6] * w2;
            o1.w = f[0][7] * w0 + f[1][7] * w1 + f[2][7] * w2;
            *(float4*)(ifl + (size_t)i * DD + c * 8)     = o0;
            *(float4*)(ifl + (size_t)i * DD + c * 8 + 4) = o1;
        }
    }
}

// ---- BPR loss (AU row-major [u][3][64], IF row-major [i][64]) ----
__global__ void k_bpr(const int* __restrict__ batch, const float* __restrict__ au,
                      const float* __restrict__ ifl, float* __restrict__ acc) {
    int t = blockIdx.x * blockDim.x + threadIdx.x;
    int idx = t >> 5;
    if (idx >= NB * 3) return;
    int lane = t & 31;
    int n = idx / 3, b = idx % 3;
    const int* bd = batch + n * 9 + b * 3;
    int u = bd[0], pos = bd[1], neg = bd[2];
    float2 uf = *(const float2*)(au + (size_t)u * 192 + b * 64 + 2 * lane);
    float2 p  = *(const float2*)(ifl + (size_t)pos * DD + 2 * lane);
    float2 q  = *(const float2*)(ifl + (size_t)neg * DD + 2 * lane);
    float s = uf.x * (p.x - q.x) + uf.y * (p.y - q.y);
    #pragma unroll
    for (int o = 16; o; o >>= 1) s += __shfl_xor_sync(0xffffffffu, s, o);
    if (lane == 0) {
        float sig = 1.0f / (1.0f + expf(-s));
        atomicAdd(acc, -logf(1e-10f + sig) * (1.0f / (float)NB));
    }
}

__global__ void k_sumsq(const float* __restrict__ x, int n, float* __restrict__ acc) {
    float s = 0.0f;
    for (int i = blockIdx.x * blockDim.x + threadIdx.x; i < n; i += gridDim.x * blockDim.x) {
        float v = x[i];
        s += v * v;
    }
    #pragma unroll
    for (int o = 16; o; o >>= 1) s += __shfl_xor_sync(0xffffffffu, s, o);
    if ((threadIdx.x & 31) == 0) atomicAdd(acc, s);
}

__global__ void k_final(const float* __restrict__ acc, float* __restrict__ out) {
    out[0] = acc[0] + 0.001f * (sqrtf(acc[1]) + sqrtf(acc[2])) / 40001.0f;
}

extern "C" void kernel_launch(void* const* d_in, const int* in_sizes, int n_in,
                              void* d_out, int out_size) {
    const float* user_emb = (const float*)d_in[0];
    const float* item_emb = (const float*)d_in[1];
    const float* W        = (const float*)d_in[2];
    const int*   eu       = (const int*)d_in[3];
    const int*   ei       = (const int*)d_in[4];
    const int*   batch    = (const int*)d_in[5];
    float* out = (float*)d_out;

    __half *X0h, *T1h, *ALLh, *TBh;
    float *AU, *IF, *rnG, *rnB, *ACC;
    int *adj, *deg, *off, *cur, *sums;
    cudaGetSymbolAddress((void**)&X0h,  d_X0h);
    cudaGetSymbolAddress((void**)&T1h,  d_T1h);
    cudaGetSymbolAddress((void**)&ALLh, d_ALLh);
    cudaGetSymbolAddress((void**)&TBh,  d_TBh);
    cudaGetSymbolAddress((void**)&AU,   d_AU);
    cudaGetSymbolAddress((void**)&IF,   d_IF);
    cudaGetSymbolAddress((void**)&rnG,  d_rnG);
    cudaGetSymbolAddress((void**)&rnB,  d_rnB);
    cudaGetSymbolAddress((void**)&ACC,  d_ACC);
    cudaGetSymbolAddress((void**)&adj,  d_adj);
    cudaGetSymbolAddress((void**)&deg,  d_deg);
    cudaGetSymbolAddress((void**)&off,  d_off);
    cudaGetSymbolAddress((void**)&cur,  d_cur);
    cudaGetSymbolAddress((void**)&sums, d_sums);

    const int NTH = 256;
    auto blocksFor = [](long threads) { return (int)((threads + 255) / 256); };

    // X0 (fp16) = concat(user_emb, item_emb)
    k_conv<<<blocksFor((long)NN * DD / 2), NTH>>>(user_emb, item_emb, X0h);

    // ---- CSR build ----
    cudaMemsetAsync(deg, 0, 3 * NN * sizeof(int));
    k_degcnt<<<blocksFor(3L * EE), NTH>>>(eu, ei, deg);
    k_scanA<<<3 * NCH, 1024>>>(deg, off, sums);
    k_scanB<<<3, 128>>>(sums);
    k_scanC<<<3 * NCH, 1024>>>(off, sums, cur);
    k_rnorm<<<blocksFor(NN), NTH>>>(deg, rnG, rnB);
    k_place<<<blocksFor(3L * EE), NTH>>>(eu, ei, cur, adj);

    // ---- global LightGCN (2 layers + combine) ----
    k_gL1<<<blocksFor((long)NN * 32), NTH>>>(X0h, T1h, off, adj, rnG);
    k_gL2c<<<blocksFor((long)NN * 32), NTH>>>(X0h, T1h, ALLh, off, adj, rnG);

    // ---- branch LightGCNs ----
    k_bL1<<<blocksFor(3L * NN * 32), NTH>>>(ALLh, TBh, off, adj, rnB);
    k_bL2f<<<blocksFor((long)NN * 32), NTH>>>(ALLh, TBh, off, adj, rnB, deg, W, AU, IF);

    // ---- losses ----
    cudaMemsetAsync(ACC, 0, 4 * sizeof(float));
    k_bpr<<<blocksFor((long)NB * 3 * 32), NTH>>>(batch, AU, IF, ACC);
    k_sumsq<<<512, NTH>>>(user_emb, NU * DD, ACC + 1);
    k_sumsq<<<512, NTH>>>(item_emb, NI * DD, ACC + 2);
    k_final<<<1, 1>>>(ACC, out);
}